// round 12
// baseline (speedup 1.0000x reference)
#include <cuda_runtime.h>
#include <cstdint>

#define NN 4096      // nodes
#define NE 4096      // hyperedges
#define NF 128       // features
#define CAP 192      // per-list capacity (max degree ~58 expected)

// ---------------- scratch (static __device__, zero-initialized) ----------
__device__ float g_theta[NN * NF];        // X @ W            (2 MB, L2-resident)
__device__ float g_U[NE * NF];            // De^-1 H^T theta  (2 MB)
__device__ float g_inv_dv[NN];
__device__ float g_inv_de[NE];
__device__ int   g_col_cnt[NE];           // 0 at entry (zero at load; spmm1 re-zeroes)
__device__ int   g_row_cnt[NN];           // 0 at entry (zero at load; spmm2 re-zeroes)
__device__ int   g_col_idx[NE * CAP];
__device__ int   g_row_idx[NN * CAP];

// ---------------- K_theta: theta = X @ W, plus diag inverses -------------
// blockIdx [0,128)   -> theta 32-row tile
// blockIdx [128,144) -> diag inverses
__global__ void __launch_bounds__(256) k_theta(const float* __restrict__ X,
                                               const float* __restrict__ W,
                                               const float* __restrict__ Dv,
                                               const float* __restrict__ De) {
    __shared__ float Xs[32][NF];
    const int b   = blockIdx.x;
    const int tid = threadIdx.x;

    if (b < 128) {
        const int row0 = b * 32;
        #pragma unroll
        for (int i = tid; i < 32 * NF; i += 256)
            Xs[i >> 7][i & 127] = X[(size_t)row0 * NF + i];
        __syncthreads();

        const int fp = tid & 63;          // float2 column
        const int rg = tid >> 6;          // row group 0..3
        const float2* __restrict__ W2 = reinterpret_cast<const float2*>(W);

        float acc[8][2];
        #pragma unroll
        for (int i = 0; i < 8; i++) { acc[i][0] = 0.f; acc[i][1] = 0.f; }

        #pragma unroll 4
        for (int k = 0; k < NF; k++) {
            float2 w = __ldg(&W2[k * 64 + fp]);
            #pragma unroll
            for (int i = 0; i < 8; i++) {
                float x = Xs[rg * 8 + i][k];
                acc[i][0] += x * w.x;
                acc[i][1] += x * w.y;
            }
        }
        #pragma unroll
        for (int i = 0; i < 8; i++) {
            int r = row0 + rg * 8 + i;
            *reinterpret_cast<float2*>(&g_theta[(size_t)r * NF + fp * 2]) =
                make_float2(acc[i][0], acc[i][1]);
        }
    } else {
        int i = (b - 128) * 256 + tid;
        if (i < NN) {
            g_inv_dv[i] = 1.0f / Dv[(size_t)i * (NN + 1)];
            g_inv_de[i] = 1.0f / De[(size_t)i * (NE + 1)];
        }
    }
}

// ---------------- K_build: CSR/CSC lists from dense H --------------------
// 1024 CTAs x 256 threads, no smem, no barriers, 48 warps/SM.
// Grid-stride: 4 outer iters x 4 front-batched int4 loads per thread.
#define BUILD_CTAS 1024
#define BUILD_THREADS (BUILD_CTAS * 256)          // 262144
__global__ void __launch_bounds__(256, 6) k_build(const float* __restrict__ H) {
    const int G = blockIdx.x * 256 + threadIdx.x;
    const int4* __restrict__ H4 = reinterpret_cast<const int4*>(H);

    #pragma unroll
    for (int iter = 0; iter < 4; iter++) {
        int4 v[4];                                 // 16 dedicated dest regs
        #pragma unroll
        for (int j = 0; j < 4; j++)
            v[j] = H4[(size_t)G + (size_t)(iter * 4 + j) * BUILD_THREADS];

        #pragma unroll
        for (int j = 0; j < 4; j++) {
            if ((v[j].x | v[j].y | v[j].z | v[j].w) != 0) {    // ~3% taken
                int f     = G + (iter * 4 + j) * BUILD_THREADS; // float4 idx
                int n     = f >> 10;
                int ebase = (f & 1023) << 2;
                int comp[4] = {v[j].x, v[j].y, v[j].z, v[j].w};
                #pragma unroll
                for (int c = 0; c < 4; c++) {
                    if (comp[c] != 0) {
                        int e = ebase + c;
                        int p = atomicAdd(&g_row_cnt[n], 1);   // 4096 addrs
                        if (p < CAP) g_row_idx[(size_t)n * CAP + p] = e;
                        int q = atomicAdd(&g_col_cnt[e], 1);   // 4096 addrs
                        if (q < CAP) g_col_idx[(size_t)e * CAP + q] = n;
                    }
                }
            }
        }
    }
}

// ---------------- SpMM gather core: warp per output row, float4 ----------
__device__ __forceinline__ float4 gather_row(const int* __restrict__ idx,
                                             int cnt,
                                             const float4* __restrict__ src,
                                             int lane) {
    float4 acc = make_float4(0.f, 0.f, 0.f, 0.f);
    int i = 0;
    for (; i + 8 <= cnt; i += 8) {
        int id[8];
        #pragma unroll
        for (int j = 0; j < 8; j++) id[j] = idx[i + j];
        float4 v[8];
        #pragma unroll
        for (int j = 0; j < 8; j++) v[j] = src[(size_t)id[j] * 32 + lane];
        #pragma unroll
        for (int j = 0; j < 8; j++) {
            acc.x += v[j].x; acc.y += v[j].y; acc.z += v[j].z; acc.w += v[j].w;
        }
    }
    for (; i < cnt; i++) {
        float4 v = src[(size_t)idx[i] * 32 + lane];
        acc.x += v.x; acc.y += v.y; acc.z += v.z; acc.w += v.w;
    }
    return acc;
}

// ---------------- K2: U[e] = inv_de[e] * sum_{n in col[e]} theta[n] ------
__global__ void __launch_bounds__(128) k_spmm1() {
    const int e    = blockIdx.x * 4 + (threadIdx.x >> 5);
    const int lane = threadIdx.x & 31;

    int cnt = g_col_cnt[e];
    if (cnt > CAP) cnt = CAP;
    float4 acc = gather_row(g_col_idx + (size_t)e * CAP, cnt,
                            reinterpret_cast<const float4*>(g_theta), lane);

    float s = g_inv_de[e];
    acc.x *= s; acc.y *= s; acc.z *= s; acc.w *= s;
    reinterpret_cast<float4*>(g_U)[(size_t)e * 32 + lane] = acc;

    if (lane == 0) g_col_cnt[e] = 0;      // leave zeroed for next launch
}

// ---------------- K3: Y[n] = inv_dv[n] * sum_{e in row[n]} U[e] ----------
__global__ void __launch_bounds__(128) k_spmm2(float* __restrict__ out) {
    const int n    = blockIdx.x * 4 + (threadIdx.x >> 5);
    const int lane = threadIdx.x & 31;

    int cnt = g_row_cnt[n];
    if (cnt > CAP) cnt = CAP;
    float4 acc = gather_row(g_row_idx + (size_t)n * CAP, cnt,
                            reinterpret_cast<const float4*>(g_U), lane);

    float s = g_inv_dv[n];
    acc.x *= s; acc.y *= s; acc.z *= s; acc.w *= s;
    reinterpret_cast<float4*>(out)[(size_t)n * 32 + lane] = acc;

    if (lane == 0) g_row_cnt[n] = 0;      // leave zeroed for next launch
}

// ---------------- launch --------------------------------------------------
extern "C" void kernel_launch(void* const* d_in, const int* in_sizes, int n_in,
                              void* d_out, int out_size) {
    const float* X  = (const float*)d_in[0];   // [4096,128]
    const float* H  = (const float*)d_in[1];   // [4096,4096]
    const float* Dv = (const float*)d_in[2];   // [4096,4096] diag
    const float* De = (const float*)d_in[3];   // [4096,4096] diag
    const float* W  = (const float*)d_in[4];   // [128,128]
    float* out = (float*)d_out;                // [4096,128]

    k_theta<<<128 + 16, 256>>>(X, W, Dv, De);
    k_build<<<BUILD_CTAS, 256>>>(H);
    k_spmm1<<<NE / 4, 128>>>();
    k_spmm2<<<NN / 4, 128>>>(out);
}

// round 13
// speedup vs baseline: 1.2746x; 1.2746x over previous
#include <cuda_runtime.h>

#define NN 4096      // nodes
#define NE 4096      // hyperedges
#define NF 128       // features
#define CAP 192      // per-list capacity (max degree ~58 expected)

// ---------------- scratch (static __device__, zero-initialized) ----------
__device__ float g_theta[NN * NF];        // X @ W            (2 MB, L2-resident)
__device__ float g_U[NE * NF];            // De^-1 H^T theta  (2 MB)
__device__ float g_inv_dv[NN];
__device__ float g_inv_de[NE];
__device__ int   g_col_cnt[NE];           // MUST be 0 at k_fused entry (zero at load;
__device__ int   g_row_cnt[NN];           //  spmm1/spmm2 re-zero after reading)
__device__ int   g_col_idx[NE * CAP];
__device__ int   g_row_idx[NN * CAP];

// ---------------- K1: fused init + theta + CSR/CSC build (R9 verbatim) ---
// blockIdx roles:  [0, 1024)             -> build: 4 H rows per CTA (64 KB stream)
//                  [1024, 1024+128)      -> theta tile
//                  [1024+128, 1024+144)  -> diag inverses
#define BUILD_CTAS 1024
__global__ void __launch_bounds__(256) k_fused(const float* __restrict__ X,
                                               const float* __restrict__ W,
                                               const float* __restrict__ H,
                                               const float* __restrict__ Dv,
                                               const float* __restrict__ De) {
    __shared__ float Xs[32][NF];          // theta branch only

    const int b   = blockIdx.x;
    const int tid = threadIdx.x;

    if (b < BUILD_CTAS) {
        // ---- build: stream 4096 float4s (4 rows), bitmask then sparse append
        const float4* __restrict__ row4 =
            reinterpret_cast<const float4*>(H) + (size_t)b * 4096;

        unsigned long long mask = 0ull;
        #pragma unroll
        for (int half = 0; half < 2; half++) {
            float4 v[8];                              // 8 LDG.128 front-batched
            #pragma unroll
            for (int j = 0; j < 8; j++)
                v[j] = row4[tid + (half * 8 + j) * 256];
            #pragma unroll
            for (int j = 0; j < 8; j++) {
                unsigned m = (v[j].x != 0.f ? 1u : 0u)
                           | (v[j].y != 0.f ? 2u : 0u)
                           | (v[j].z != 0.f ? 4u : 0u)
                           | (v[j].w != 0.f ? 8u : 0u);
                mask |= (unsigned long long)m << ((half * 8 + j) * 4);
            }
        }

        // ~0.5 set bits per thread on average
        while (mask) {
            int bit = __ffsll((long long)mask) - 1;
            mask &= mask - 1;
            int kk  = bit >> 2;
            int j   = bit & 3;
            int off = kk * 256 + tid;                 // float4 index within chunk
            int n   = b * 4 + (off >> 10);
            int e   = ((off << 2) | j) & (NE - 1);

            int p = atomicAdd(&g_row_cnt[n], 1);      // spread over 4096 addrs
            if (p < CAP) g_row_idx[(size_t)n * CAP + p] = e;
            int q = atomicAdd(&g_col_cnt[e], 1);      // spread over 4096 addrs
            if (q < CAP) g_col_idx[(size_t)e * CAP + q] = n;
        }

    } else if (b < BUILD_CTAS + 128) {
        // ---- theta = X @ W : 32-row x 128-col tile --------------------
        const int row0 = (b - BUILD_CTAS) * 32;
        #pragma unroll
        for (int i = tid; i < 32 * NF; i += 256)
            Xs[i >> 7][i & 127] = X[(size_t)row0 * NF + i];
        __syncthreads();

        const int fp = tid & 63;          // float2 column
        const int rg = tid >> 6;          // row group 0..3
        const float2* __restrict__ W2 = reinterpret_cast<const float2*>(W);

        float acc[8][2];
        #pragma unroll
        for (int i = 0; i < 8; i++) { acc[i][0] = 0.f; acc[i][1] = 0.f; }

        #pragma unroll 4
        for (int k = 0; k < NF; k++) {
            float2 w = __ldg(&W2[k * 64 + fp]);
            #pragma unroll
            for (int i = 0; i < 8; i++) {
                float x = Xs[rg * 8 + i][k];
                acc[i][0] += x * w.x;
                acc[i][1] += x * w.y;
            }
        }
        #pragma unroll
        for (int i = 0; i < 8; i++) {
            int r = row0 + rg * 8 + i;
            *reinterpret_cast<float2*>(&g_theta[(size_t)r * NF + fp * 2]) =
                make_float2(acc[i][0], acc[i][1]);
        }

    } else {
        // ---- diagonal inverses ----------------------------------------
        int i = (b - BUILD_CTAS - 128) * 256 + tid;
        if (i < NN) {
            g_inv_dv[i] = 1.0f / Dv[(size_t)i * (NN + 1)];
            g_inv_de[i] = 1.0f / De[(size_t)i * (NE + 1)];
        }
    }
}

// ---------------- SpMM gather core: 4 warps per row, 1 float per lane ----
// Each warp covers 32 features: addr = row*128 + part*32 + lane.
__device__ __forceinline__ float gather_part(const int* __restrict__ idx,
                                             int cnt,
                                             const float* __restrict__ src) {
    float acc = 0.0f;
    int i = 0;
    for (; i + 8 <= cnt; i += 8) {
        int id[8];
        #pragma unroll
        for (int j = 0; j < 8; j++) id[j] = idx[i + j];
        float v[8];
        #pragma unroll
        for (int j = 0; j < 8; j++) v[j] = src[(size_t)id[j] * NF];
        #pragma unroll
        for (int j = 0; j < 8; j++) acc += v[j];
    }
    for (; i < cnt; i++) acc += src[(size_t)idx[i] * NF];
    return acc;
}

// ---------------- K2: U[e] = inv_de[e] * sum_{n in col[e]} theta[n] ------
// CTA = 256 threads = 8 warps = 2 edges x 4 feature-parts.
__global__ void __launch_bounds__(256) k_spmm1() {
    __shared__ int s_cnt[2];
    const int tid  = threadIdx.x;
    const int warp = tid >> 5;
    const int lane = tid & 31;
    const int lr   = warp >> 2;           // local row 0..1
    const int part = warp & 3;            // feature part 0..3
    const int e    = blockIdx.x * 2 + lr;

    if (tid < 2) s_cnt[tid] = g_col_cnt[blockIdx.x * 2 + tid];
    __syncthreads();
    if (tid < 2) g_col_cnt[blockIdx.x * 2 + tid] = 0;   // safe: all read via smem

    int cnt = s_cnt[lr];
    if (cnt > CAP) cnt = CAP;

    float acc = gather_part(g_col_idx + (size_t)e * CAP, cnt,
                            g_theta + part * 32 + lane);
    g_U[(size_t)e * NF + part * 32 + lane] = acc * g_inv_de[e];
}

// ---------------- K3: Y[n] = inv_dv[n] * sum_{e in row[n]} U[e] ----------
__global__ void __launch_bounds__(256) k_spmm2(float* __restrict__ out) {
    __shared__ int s_cnt[2];
    const int tid  = threadIdx.x;
    const int warp = tid >> 5;
    const int lane = tid & 31;
    const int lr   = warp >> 2;
    const int part = warp & 3;
    const int n    = blockIdx.x * 2 + lr;

    if (tid < 2) s_cnt[tid] = g_row_cnt[blockIdx.x * 2 + tid];
    __syncthreads();
    if (tid < 2) g_row_cnt[blockIdx.x * 2 + tid] = 0;   // safe: all read via smem

    int cnt = s_cnt[lr];
    if (cnt > CAP) cnt = CAP;

    float acc = gather_part(g_row_idx + (size_t)n * CAP, cnt,
                            g_U + part * 32 + lane);
    out[(size_t)n * NF + part * 32 + lane] = acc * g_inv_dv[n];
}

// ---------------- launch --------------------------------------------------
extern "C" void kernel_launch(void* const* d_in, const int* in_sizes, int n_in,
                              void* d_out, int out_size) {
    const float* X  = (const float*)d_in[0];   // [4096,128]
    const float* H  = (const float*)d_in[1];   // [4096,4096]
    const float* Dv = (const float*)d_in[2];   // [4096,4096] diag
    const float* De = (const float*)d_in[3];   // [4096,4096] diag
    const float* W  = (const float*)d_in[4];   // [128,128]
    float* out = (float*)d_out;                // [4096,128]

    k_fused<<<BUILD_CTAS + 128 + 16, 256>>>(X, W, H, Dv, De);
    k_spmm1<<<NE / 2, 256>>>();
    k_spmm2<<<NN / 2, 256>>>(out);
}

// round 14
// speedup vs baseline: 1.6455x; 1.2910x over previous
#include <cuda_runtime.h>

#define NN 4096      // nodes
#define NE 4096      // hyperedges
#define NF 128       // features
#define CAP 192      // per-list capacity (max degree ~58 expected)

#define THETA_CTAS 144          // 128 theta tiles + 16 inverse CTAs (run first)
#define BUILD_CTAS 1024
#define PAIR_MAX   1024         // staging capacity (avg ~128 nz per 4-row CTA)

// ---------------- scratch (static __device__, zero-initialized) ----------
__device__ float g_theta[NN * NF];        // X @ W            (2 MB, L2-resident)
__device__ float g_U[NE * NF];            // De^-1 H^T theta  (2 MB)
__device__ float g_inv_dv[NN];
__device__ float g_inv_de[NE];
__device__ int   g_col_cnt[NE];           // MUST be 0 at k_fused entry (zero at load;
__device__ int   g_row_cnt[NN];           //  spmm1/spmm2 re-zero after reading)
__device__ int   g_col_idx[NE * CAP];
__device__ int   g_row_idx[NN * CAP];

// ---------------- K1: fused theta + init + CSR/CSC build -----------------
// blockIdx roles:  [0, 128)                  -> theta tile
//                  [128, 144)                -> diag inverses
//                  [144, 144+1024)           -> build: 4 H rows per CTA
__global__ void __launch_bounds__(256) k_fused(const float* __restrict__ X,
                                               const float* __restrict__ W,
                                               const float* __restrict__ H,
                                               const float* __restrict__ Dv,
                                               const float* __restrict__ De) {
    __shared__ __align__(16) char s_mem[16384];   // union: Xs | pair staging
    __shared__ int s_cnt;

    const int b   = blockIdx.x;
    const int tid = threadIdx.x;

    if (b >= THETA_CTAS) {
        // ---- build: stream 4 rows (64 KB), two-phase append -----------
        const int b2 = b - THETA_CTAS;
        const float4* __restrict__ row4 =
            reinterpret_cast<const float4*>(H) + (size_t)b2 * 4096;
        unsigned* s_pairs = reinterpret_cast<unsigned*>(s_mem);

        if (tid == 0) s_cnt = 0;

        unsigned long long mask = 0ull;
        #pragma unroll
        for (int half = 0; half < 2; half++) {
            float4 v[8];                              // 8 LDG.128 front-batched
            #pragma unroll
            for (int j = 0; j < 8; j++)
                v[j] = row4[tid + (half * 8 + j) * 256];
            #pragma unroll
            for (int j = 0; j < 8; j++) {
                unsigned m = (v[j].x != 0.f ? 1u : 0u)
                           | (v[j].y != 0.f ? 2u : 0u)
                           | (v[j].z != 0.f ? 4u : 0u)
                           | (v[j].w != 0.f ? 8u : 0u);
                mask |= (unsigned long long)m << ((half * 8 + j) * 4);
            }
        }
        __syncthreads();                  // s_cnt = 0 visible

        // Phase 1: stage (row_local, e) pairs in smem — no global atomics
        while (mask) {
            int bit = __ffsll((long long)mask) - 1;
            mask &= mask - 1;
            int kk  = bit >> 2;
            int j   = bit & 3;
            int off = kk * 256 + tid;                 // float4 index in chunk
            unsigned local = (unsigned)(off >> 10);   // row 0..3
            unsigned e     = (unsigned)(((off << 2) | j) & (NE - 1));
            int p = atomicAdd(&s_cnt, 1);             // smem atomic (~30 cyc)
            if (p < PAIR_MAX) s_pairs[p] = (local << 12) | e;
        }
        __syncthreads();

        // Phase 2: parallel global appends — one atomic round-trip, not a chain
        int tot = s_cnt < PAIR_MAX ? s_cnt : PAIR_MAX;
        for (int i = tid; i < tot; i += 256) {
            unsigned pr = s_pairs[i];
            int n = b2 * 4 + (int)(pr >> 12);
            int e = (int)(pr & (NE - 1));
            int p = atomicAdd(&g_row_cnt[n], 1);      // 4096 spread addrs
            if (p < CAP) g_row_idx[(size_t)n * CAP + p] = e;
            int q = atomicAdd(&g_col_cnt[e], 1);      // 4096 spread addrs
            if (q < CAP) g_col_idx[(size_t)e * CAP + q] = n;
        }

    } else if (b < 128) {
        // ---- theta = X @ W : 32-row x 128-col tile --------------------
        float (*Xs)[NF] = reinterpret_cast<float (*)[NF]>(s_mem);
        const int row0 = b * 32;
        #pragma unroll
        for (int i = tid; i < 32 * NF; i += 256)
            Xs[i >> 7][i & 127] = X[(size_t)row0 * NF + i];
        __syncthreads();

        const int fp = tid & 63;          // float2 column
        const int rg = tid >> 6;          // row group 0..3
        const float2* __restrict__ W2 = reinterpret_cast<const float2*>(W);

        float acc[8][2];
        #pragma unroll
        for (int i = 0; i < 8; i++) { acc[i][0] = 0.f; acc[i][1] = 0.f; }

        #pragma unroll 4
        for (int k = 0; k < NF; k++) {
            float2 w = __ldg(&W2[k * 64 + fp]);
            #pragma unroll
            for (int i = 0; i < 8; i++) {
                float x = Xs[rg * 8 + i][k];
                acc[i][0] += x * w.x;
                acc[i][1] += x * w.y;
            }
        }
        #pragma unroll
        for (int i = 0; i < 8; i++) {
            int r = row0 + rg * 8 + i;
            *reinterpret_cast<float2*>(&g_theta[(size_t)r * NF + fp * 2]) =
                make_float2(acc[i][0], acc[i][1]);
        }

    } else {
        // ---- diagonal inverses ----------------------------------------
        int i = (b - 128) * 256 + tid;
        if (i < NN) {
            g_inv_dv[i] = 1.0f / Dv[(size_t)i * (NN + 1)];
            g_inv_de[i] = 1.0f / De[(size_t)i * (NE + 1)];
        }
    }
}

// ---------------- SpMM gather core: 4 warps per row, 1 float per lane ----
__device__ __forceinline__ float gather_part(const int* __restrict__ idx,
                                             int cnt,
                                             const float* __restrict__ src) {
    float acc = 0.0f;
    int i = 0;
    for (; i + 8 <= cnt; i += 8) {
        int id[8];
        #pragma unroll
        for (int j = 0; j < 8; j++) id[j] = idx[i + j];
        float v[8];
        #pragma unroll
        for (int j = 0; j < 8; j++) v[j] = src[(size_t)id[j] * NF];
        #pragma unroll
        for (int j = 0; j < 8; j++) acc += v[j];
    }
    for (; i < cnt; i++) acc += src[(size_t)idx[i] * NF];
    return acc;
}

// ---------------- K2: U[e] = inv_de[e] * sum_{n in col[e]} theta[n] ------
// CTA = 256 threads = 8 warps = 2 edges x 4 feature-parts.
__global__ void __launch_bounds__(256) k_spmm1() {
    __shared__ int s_cnt2[2];
    const int tid  = threadIdx.x;
    const int warp = tid >> 5;
    const int lane = tid & 31;
    const int lr   = warp >> 2;           // local row 0..1
    const int part = warp & 3;            // feature part 0..3
    const int e    = blockIdx.x * 2 + lr;

    if (tid < 2) s_cnt2[tid] = g_col_cnt[blockIdx.x * 2 + tid];
    __syncthreads();
    if (tid < 2) g_col_cnt[blockIdx.x * 2 + tid] = 0;   // safe: all read via smem

    int cnt = s_cnt2[lr];
    if (cnt > CAP) cnt = CAP;

    float acc = gather_part(g_col_idx + (size_t)e * CAP, cnt,
                            g_theta + part * 32 + lane);
    g_U[(size_t)e * NF + part * 32 + lane] = acc * g_inv_de[e];
}

// ---------------- K3: Y[n] = inv_dv[n] * sum_{e in row[n]} U[e] ----------
__global__ void __launch_bounds__(256) k_spmm2(float* __restrict__ out) {
    __shared__ int s_cnt2[2];
    const int tid  = threadIdx.x;
    const int warp = tid >> 5;
    const int lane = tid & 31;
    const int lr   = warp >> 2;
    const int part = warp & 3;
    const int n    = blockIdx.x * 2 + lr;

    if (tid < 2) s_cnt2[tid] = g_row_cnt[blockIdx.x * 2 + tid];
    __syncthreads();
    if (tid < 2) g_row_cnt[blockIdx.x * 2 + tid] = 0;   // safe: all read via smem

    int cnt = s_cnt2[lr];
    if (cnt > CAP) cnt = CAP;

    float acc = gather_part(g_row_idx + (size_t)n * CAP, cnt,
                            g_U + part * 32 + lane);
    out[(size_t)n * NF + part * 32 + lane] = acc * g_inv_dv[n];
}

// ---------------- launch --------------------------------------------------
extern "C" void kernel_launch(void* const* d_in, const int* in_sizes, int n_in,
                              void* d_out, int out_size) {
    const float* X  = (const float*)d_in[0];   // [4096,128]
    const float* H  = (const float*)d_in[1];   // [4096,4096]
    const float* Dv = (const float*)d_in[2];   // [4096,4096] diag
    const float* De = (const float*)d_in[3];   // [4096,4096] diag
    const float* W  = (const float*)d_in[4];   // [128,128]
    float* out = (float*)d_out;                // [4096,128]

    k_fused<<<THETA_CTAS + BUILD_CTAS, 256>>>(X, W, H, Dv, De);
    k_spmm1<<<NE / 2, 256>>>();
    k_spmm2<<<NN / 2, 256>>>(out);
}